// round 1
// baseline (speedup 1.0000x reference)
#include <cuda_runtime.h>
#include <math.h>

#define Hdim   768
#define Edim   8
#define Fdim   3072
#define EFdim  (Edim * Fdim)
#define Ttok   4096
#define TKa    8192          // Ttok * 2 assignments
#define BLKpad 16

// ---------------- scratch (device globals; no allocation) ----------------
__device__ int   g_sel[TKa];
__device__ int   g_counts[Edim];
__device__ int   g_last[Edim];
__device__ int   g_pad[Edim];
__device__ int   g_segoff[Edim];
__device__ int   g_cursor[Edim];
__device__ int   g_rowTok[TKa];
__device__ float g_rowMult[TKa];
__device__ float g_hbuf[(size_t)TKa * Fdim];   // 96 MB gelu activations
__device__ float g_logits_scratch[Ttok * Edim];

// ---------------- zero output region ----------------
__global__ void zero_kernel(float4* out, int n4) {
    int i = blockIdx.x * blockDim.x + threadIdx.x;
    if (i < n4) out[i] = make_float4(0.f, 0.f, 0.f, 0.f);
}

// ---------------- router: logits + top-2 selection ----------------
__global__ void router_kernel(const float* __restrict__ x,
                              const float* __restrict__ rw,
                              float* __restrict__ logits_out) {
    int t   = blockIdx.x;
    int tid = threadIdx.x;
    const float* xr = x + (size_t)t * Hdim;

    float acc[Edim];
#pragma unroll
    for (int e = 0; e < Edim; e++) acc[e] = 0.f;
    for (int k = tid; k < Hdim; k += 256) {
        float xv = xr[k];
#pragma unroll
        for (int e = 0; e < Edim; e++) acc[e] += xv * rw[e * Hdim + k];
    }
    __shared__ float sh[Edim][256];
#pragma unroll
    for (int e = 0; e < Edim; e++) sh[e][tid] = acc[e];
    __syncthreads();
    for (int s = 128; s > 0; s >>= 1) {
        if (tid < s) {
#pragma unroll
            for (int e = 0; e < Edim; e++) sh[e][tid] += sh[e][tid + s];
        }
        __syncthreads();
    }
    if (tid == 0) {
        float lg[Edim];
#pragma unroll
        for (int e = 0; e < Edim; e++) {
            lg[e] = sh[e][0];
            logits_out[t * Edim + e] = lg[e];
        }
        // top-2 by logit (softmax monotone); strict '>' keeps lower index on ties (jax top_k)
        int i0 = 0;
#pragma unroll
        for (int e = 1; e < Edim; e++) if (lg[e] > lg[i0]) i0 = e;
        int i1 = (i0 == 0) ? 1 : 0;
#pragma unroll
        for (int e = 0; e < Edim; e++) if (e != i0 && lg[e] > lg[i1]) i1 = e;
        g_sel[t * 2 + 0] = i0;
        g_sel[t * 2 + 1] = i1;
    }
}

// ---------------- assignment pass: counts, last, pad, sorted row lists ----------------
__global__ void assign_kernel() {
    int tid = threadIdx.x;
    if (tid < Edim) { g_counts[tid] = 0; g_last[tid] = -1; }
    __syncthreads();
    for (int a = tid; a < TKa; a += blockDim.x) {
        int e = g_sel[a];
        atomicAdd(&g_counts[e], 1);
        atomicMax(&g_last[e], a);
    }
    __syncthreads();
    if (tid == 0) {
        int off = 0;
        for (int e = 0; e < Edim; e++) {
            g_segoff[e] = off;
            g_cursor[e] = off;
            off += g_counts[e];
            g_pad[e] = (BLKpad - (g_counts[e] % BLKpad)) % BLKpad;
        }
    }
    __syncthreads();
    for (int a = tid; a < TKa; a += blockDim.x) {
        int e   = g_sel[a];
        int pos = atomicAdd(&g_cursor[e], 1);
        g_rowTok[pos]  = a >> 1;
        g_rowMult[pos] = (a == g_last[e]) ? (1.0f + (float)g_pad[e]) : 1.0f;
    }
}

__device__ __forceinline__ float gelu_exact(float v) {
    return 0.5f * v * (1.0f + erff(v * 0.7071067811865476f));
}

// ---------------- GEMM1: hbuf = gelu( Xg @ W1_e )  [rows x 3072, K=768] ----------------
// tile 64x64, BK=16, 256 threads, 4x4 microtile
__global__ void gemm1_kernel(const float* __restrict__ x,
                             const float* __restrict__ w1) {
    int e   = blockIdx.z;
    int cnt = g_counts[e];
    int m0  = blockIdx.y * 64;
    if (m0 >= cnt) return;
    int base = g_segoff[e];
    int n0   = blockIdx.x * 64;

    __shared__ float As[16][68];   // [k][m], padded (272B row, 16B-aligned)
    __shared__ float Bs[16][64];   // [k][n]

    int tid = threadIdx.x;
    int lm  = tid >> 2;            // 0..63 row within tile
    int lk4 = (tid & 3) * 4;       // 0,4,8,12
    int row = m0 + lm;
    bool mvalid = (row < cnt);
    int tok = mvalid ? g_rowTok[base + row] : g_rowTok[base];
    const float* aptr = x + (size_t)tok * Hdim + lk4;

    int bk  = tid >> 4;            // 0..15
    int bn4 = (tid & 15) * 4;      // 0..60
    const float* bptr = w1 + (size_t)bk * EFdim + (size_t)e * Fdim + n0 + bn4;

    int tx = tid & 15, ty = tid >> 4;
    float acc[4][4];
#pragma unroll
    for (int i = 0; i < 4; i++)
#pragma unroll
        for (int j = 0; j < 4; j++) acc[i][j] = 0.f;

    for (int k0 = 0; k0 < Hdim; k0 += 16) {
        float4 av = mvalid ? *(const float4*)aptr : make_float4(0.f, 0.f, 0.f, 0.f);
        As[lk4 + 0][lm] = av.x;
        As[lk4 + 1][lm] = av.y;
        As[lk4 + 2][lm] = av.z;
        As[lk4 + 3][lm] = av.w;
        *(float4*)&Bs[bk][bn4] = *(const float4*)bptr;
        __syncthreads();
#pragma unroll
        for (int kk = 0; kk < 16; kk++) {
            float4 a4 = *(const float4*)&As[kk][ty * 4];
            float4 b4 = *(const float4*)&Bs[kk][tx * 4];
            float a[4] = {a4.x, a4.y, a4.z, a4.w};
            float b[4] = {b4.x, b4.y, b4.z, b4.w};
#pragma unroll
            for (int i = 0; i < 4; i++)
#pragma unroll
                for (int j = 0; j < 4; j++) acc[i][j] += a[i] * b[j];
        }
        __syncthreads();
        aptr += 16;
        bptr += (size_t)16 * EFdim;
    }

#pragma unroll
    for (int i = 0; i < 4; i++) {
        int m = m0 + ty * 4 + i;
        if (m < cnt) {
            float4 o;
            o.x = gelu_exact(acc[i][0]);
            o.y = gelu_exact(acc[i][1]);
            o.z = gelu_exact(acc[i][2]);
            o.w = gelu_exact(acc[i][3]);
            *(float4*)&g_hbuf[(size_t)(base + m) * Fdim + n0 + tx * 4] = o;
        }
    }
}

// ---------------- GEMM2: out[tok] += mult * ( hbuf @ W2_e )  [rows x 768, K=3072] ----------------
__global__ void gemm2_kernel(const float* __restrict__ w2,
                             float* __restrict__ out) {
    int e   = blockIdx.z;
    int cnt = g_counts[e];
    int m0  = blockIdx.y * 64;
    if (m0 >= cnt) return;
    int base = g_segoff[e];
    int n0   = blockIdx.x * 64;

    __shared__ float As[16][68];
    __shared__ float Bs[16][64];

    int tid = threadIdx.x;
    int lm  = tid >> 2;
    int lk4 = (tid & 3) * 4;
    int row = m0 + lm;
    bool mvalid = (row < cnt);
    const float* aptr = mvalid ? (g_hbuf + (size_t)(base + row) * Fdim + lk4)
                               : (g_hbuf + lk4);

    int bk  = tid >> 4;
    int bn4 = (tid & 15) * 4;
    const float* bptr = w2 + ((size_t)e * Fdim + bk) * Hdim + n0 + bn4;

    int tx = tid & 15, ty = tid >> 4;
    float acc[4][4];
#pragma unroll
    for (int i = 0; i < 4; i++)
#pragma unroll
        for (int j = 0; j < 4; j++) acc[i][j] = 0.f;

    for (int k0 = 0; k0 < Fdim; k0 += 16) {
        float4 av = *(const float4*)aptr;
        As[lk4 + 0][lm] = av.x;
        As[lk4 + 1][lm] = av.y;
        As[lk4 + 2][lm] = av.z;
        As[lk4 + 3][lm] = av.w;
        *(float4*)&Bs[bk][bn4] = *(const float4*)bptr;
        __syncthreads();
#pragma unroll
        for (int kk = 0; kk < 16; kk++) {
            float4 a4 = *(const float4*)&As[kk][ty * 4];
            float4 b4 = *(const float4*)&Bs[kk][tx * 4];
            float a[4] = {a4.x, a4.y, a4.z, a4.w};
            float b[4] = {b4.x, b4.y, b4.z, b4.w};
#pragma unroll
            for (int i = 0; i < 4; i++)
#pragma unroll
                for (int j = 0; j < 4; j++) acc[i][j] += a[i] * b[j];
        }
        __syncthreads();
        aptr += 16;
        bptr += (size_t)16 * Hdim;
    }

#pragma unroll
    for (int i = 0; i < 4; i++) {
        int m = m0 + ty * 4 + i;
        if (m < cnt) {
            int   tok  = g_rowTok[base + m];
            float mult = g_rowMult[base + m];
            float* op = out + (size_t)tok * Hdim + n0 + tx * 4;
#pragma unroll
            for (int j = 0; j < 4; j++) atomicAdd(&op[j], mult * acc[i][j]);
        }
    }
}

// ---------------- launch ----------------
extern "C" void kernel_launch(void* const* d_in, const int* in_sizes, int n_in,
                              void* d_out, int out_size) {
    const float* x  = (const float*)d_in[0];
    const float* rw = (const float*)d_in[1];
    const float* w1 = (const float*)d_in[2];
    const float* w2 = (const float*)d_in[3];
    float* out = (float*)d_out;

    // tuple output: (moe_out [T,H], router_logits [T,E]) flattened & concatenated
    float* logits_out;
    if (out_size >= Ttok * Hdim + Ttok * Edim) {
        logits_out = out + (size_t)Ttok * Hdim;
    } else {
        void* p = nullptr;
        cudaGetSymbolAddress(&p, g_logits_scratch);
        logits_out = (float*)p;
    }

    int n4 = (Ttok * Hdim) / 4;
    zero_kernel<<<(n4 + 255) / 256, 256>>>((float4*)out, n4);
    router_kernel<<<Ttok, 256>>>(x, rw, logits_out);
    assign_kernel<<<1, 256>>>();
    gemm1_kernel<<<dim3(Fdim / 64, Ttok / 64, Edim), 256>>>(x, w1);
    gemm2_kernel<<<dim3(Hdim / 64, Ttok / 64, Edim), 256>>>(w2, out);
}

// round 6
// speedup vs baseline: 2.1025x; 2.1025x over previous
#include <cuda_runtime.h>
#include <cuda_bf16.h>
#include <math.h>
#include <stdint.h>

#define Hdim   768
#define Edim   8
#define Fdim   3072
#define EFdim  (Edim * Fdim)
#define Ttok   4096
#define TKa    8192          // Ttok * 2 assignments
#define TKaP   9216          // padded to 128-row tiles
#define BLKpad 16
#define MAXTILES 72

// ---------------- scratch (device globals; no allocation) ----------------
__device__ int   g_sel[TKa];
__device__ int   g_counts[Edim];
__device__ int   g_last[Edim];
__device__ int   g_pad[Edim];
__device__ int   g_segoff[Edim];
__device__ int   g_cursor[Edim];
__device__ int   g_rowTok[TKaP];
__device__ float g_rowMult[TKaP];
__device__ int   g_tileE[MAXTILES];
__device__ int   g_tileM0[MAXTILES];
__device__ int   g_nTiles;
__device__ float g_logits_scratch[Ttok * Edim];

// bf16 hi/lo split operands — uint4 arrays for guaranteed 16B alignment
__device__ uint4 g_xgH4[(size_t)TKaP * Hdim / 8];
__device__ uint4 g_xgL4[(size_t)TKaP * Hdim / 8];
__device__ uint4 g_hbH4[(size_t)TKaP * Fdim / 8];
__device__ uint4 g_hbL4[(size_t)TKaP * Fdim / 8];
__device__ uint4 g_w1H4[(size_t)Hdim * EFdim / 8];
__device__ uint4 g_w1L4[(size_t)Hdim * EFdim / 8];
__device__ uint4 g_w2H4[(size_t)EFdim * Hdim / 8];
__device__ uint4 g_w2L4[(size_t)EFdim * Hdim / 8];
// NOTE: these macros are valid ONLY in device code (never evaluate on host!)
#define g_xgH ((unsigned short*)g_xgH4)
#define g_xgL ((unsigned short*)g_xgL4)
#define g_hbH ((unsigned short*)g_hbH4)
#define g_hbL ((unsigned short*)g_hbL4)
#define g_w1H ((unsigned short*)g_w1H4)
#define g_w1L ((unsigned short*)g_w1L4)
#define g_w2H ((unsigned short*)g_w2H4)
#define g_w2L ((unsigned short*)g_w2L4)

// ================= helpers =================
__device__ __forceinline__ uint32_t smem_u32(const void* p) {
    uint32_t a;
    asm("{ .reg .u64 t; cvta.to.shared.u64 t, %1; cvt.u32.u64 %0, t; }" : "=r"(a) : "l"(p));
    return a;
}
__device__ __forceinline__ void split2(float v, unsigned short& h, unsigned short& l) {
    __nv_bfloat16 hb = __float2bfloat16(v);
    float r = v - __bfloat162float(hb);
    h = __bfloat16_as_ushort(hb);
    l = __bfloat16_as_ushort(__float2bfloat16(r));
}
__device__ __forceinline__ float gelu_exact(float v) {
    return 0.5f * v * (1.0f + erff(v * 0.7071067811865476f));
}
__device__ __forceinline__ void ldm_x4(uint32_t* r, uint32_t addr) {
    asm volatile("ldmatrix.sync.aligned.m8n8.x4.shared.b16 {%0,%1,%2,%3}, [%4];"
                 : "=r"(r[0]), "=r"(r[1]), "=r"(r[2]), "=r"(r[3]) : "r"(addr));
}
__device__ __forceinline__ void ldm_x4t(uint32_t* r, uint32_t addr) {
    asm volatile("ldmatrix.sync.aligned.m8n8.x4.trans.shared.b16 {%0,%1,%2,%3}, [%4];"
                 : "=r"(r[0]), "=r"(r[1]), "=r"(r[2]), "=r"(r[3]) : "r"(addr));
}
__device__ __forceinline__ void mma16816(float* d, const uint32_t* a, const uint32_t* b) {
    asm volatile("mma.sync.aligned.m16n8k16.row.col.f32.bf16.bf16.f32 "
                 "{%0,%1,%2,%3}, {%4,%5,%6,%7}, {%8,%9}, {%0,%1,%2,%3};"
                 : "+f"(d[0]), "+f"(d[1]), "+f"(d[2]), "+f"(d[3])
                 : "r"(a[0]), "r"(a[1]), "r"(a[2]), "r"(a[3]), "r"(b[0]), "r"(b[1]));
}

// ---------------- zero output ----------------
__global__ void zero_kernel(float4* out, int n4) {
    int i = blockIdx.x * blockDim.x + threadIdx.x;
    if (i < n4) out[i] = make_float4(0.f, 0.f, 0.f, 0.f);
}

// ---------------- router ----------------
__global__ void router_kernel(const float* __restrict__ x,
                              const float* __restrict__ rw,
                              float* __restrict__ logits_out) {
    int t = blockIdx.x, tid = threadIdx.x;
    const float* xr = x + (size_t)t * Hdim;
    float acc[Edim];
#pragma unroll
    for (int e = 0; e < Edim; e++) acc[e] = 0.f;
    for (int k = tid; k < Hdim; k += 256) {
        float xv = xr[k];
#pragma unroll
        for (int e = 0; e < Edim; e++) acc[e] += xv * rw[e * Hdim + k];
    }
    __shared__ float sh[Edim][256];
#pragma unroll
    for (int e = 0; e < Edim; e++) sh[e][tid] = acc[e];
    __syncthreads();
    for (int s = 128; s > 0; s >>= 1) {
        if (tid < s) {
#pragma unroll
            for (int e = 0; e < Edim; e++) sh[e][tid] += sh[e][tid + s];
        }
        __syncthreads();
    }
    if (tid == 0) {
        float lg[Edim];
#pragma unroll
        for (int e = 0; e < Edim; e++) { lg[e] = sh[e][0]; logits_out[t * Edim + e] = lg[e]; }
        int i0 = 0;
#pragma unroll
        for (int e = 1; e < Edim; e++) if (lg[e] > lg[i0]) i0 = e;
        int i1 = (i0 == 0) ? 1 : 0;
#pragma unroll
        for (int e = 0; e < Edim; e++) if (e != i0 && lg[e] > lg[i1]) i1 = e;
        g_sel[t * 2 + 0] = i0;
        g_sel[t * 2 + 1] = i1;
    }
}

// ---------------- assignment ----------------
__global__ void assign_kernel() {
    int tid = threadIdx.x;
    if (tid < Edim) { g_counts[tid] = 0; g_last[tid] = -1; }
    for (int i = tid; i < TKaP; i += 256) { g_rowTok[i] = -1; g_rowMult[i] = 0.f; }
    __syncthreads();
    for (int a = tid; a < TKa; a += 256) {
        int e = g_sel[a];
        atomicAdd(&g_counts[e], 1);
        atomicMax(&g_last[e], a);
    }
    __syncthreads();
    if (tid == 0) {
        int off = 0, nt = 0;
        for (int e = 0; e < Edim; e++) {
            int c = g_counts[e];
            g_segoff[e] = off; g_cursor[e] = off;
            g_pad[e] = (BLKpad - (c % BLKpad)) % BLKpad;
            int ntile = (c + 127) / 128;
            for (int t = 0; t < ntile; t++) { g_tileE[nt] = e; g_tileM0[nt] = off + t * 128; nt++; }
            off += ntile * 128;
        }
        g_nTiles = nt;
    }
    __syncthreads();
    for (int a = tid; a < TKa; a += 256) {
        int e = g_sel[a];
        int pos = atomicAdd(&g_cursor[e], 1);
        g_rowTok[pos] = a >> 1;
        g_rowMult[pos] = (a == g_last[e]) ? (1.0f + (float)g_pad[e]) : 1.0f;
    }
}

// ---------------- gather x rows, split hi/lo ----------------
__global__ void gather_split_kernel(const float* __restrict__ x) {
    int r = blockIdx.x;
    int tok = g_rowTok[r];
    int c2 = threadIdx.x;               // 384 threads, one float2 each
    float2 v = (tok >= 0) ? ((const float2*)(x + (size_t)tok * Hdim))[c2]
                          : make_float2(0.f, 0.f);
    unsigned short h0, l0, h1, l1;
    split2(v.x, h0, l0); split2(v.y, h1, l1);
    ((unsigned*)(g_xgH + (size_t)r * Hdim))[c2] = (unsigned)h0 | ((unsigned)h1 << 16);
    ((unsigned*)(g_xgL + (size_t)r * Hdim))[c2] = (unsigned)l0 | ((unsigned)l1 << 16);
}

// ---------------- elementwise weight split ----------------
// FIX R6: destination symbols resolved in DEVICE code (template W selects),
// never passed as host-evaluated __device__ symbol addresses.
template<int W>
__global__ void split_w_kernel(const float* __restrict__ w, size_t n2) {
    size_t i = (size_t)blockIdx.x * blockDim.x + threadIdx.x;
    if (i < n2) {
        unsigned short* h = (W == 1) ? g_w1H : g_w2H;
        unsigned short* l = (W == 1) ? g_w1L : g_w2L;
        float2 v = ((const float2*)w)[i];
        unsigned short h0, l0, h1, l1;
        split2(v.x, h0, l0); split2(v.y, h1, l1);
        ((unsigned*)h)[i] = (unsigned)h0 | ((unsigned)h1 << 16);
        ((unsigned*)l)[i] = (unsigned)l0 | ((unsigned)l1 << 16);
    }
}

// ================= grouped bf16x3 HMMA GEMM =================
// BM=128, BN=128, BK=16. 8 warps: warp (wm,wn) = 32x64 tile.
// Synchronous LDG -> register prefetch -> STS, double-buffered smem.
#define ASTRIDE 48                       // 32B data + 16B pad
#define BSTRIDE 272                      // 256B data + 16B pad
#define A_BYTES (128 * ASTRIDE)          // 6144
#define B_BYTES (16 * BSTRIDE)           // 4352
#define STAGE   (2 * A_BYTES + 2 * B_BYTES)  // 20992
// stage layout: Ah[0,6144) Al[6144,12288) Bh[12288,16640) Bl[16640,20992)

template<int MODE>
__global__ void __launch_bounds__(256) mma_kernel(float* __restrict__ dout) {
    constexpr int Kd = (MODE == 1) ? Hdim : Fdim;
    constexpr int NK = Kd / 16;

    int tileIdx = blockIdx.y;
    if (tileIdx >= g_nTiles) return;
    int e  = g_tileE[tileIdx];
    int m0 = g_tileM0[tileIdx];
    int n0 = blockIdx.x * 128;

    __shared__ __align__(16) char smem[2 * STAGE];
    uint32_t sb = smem_u32(smem);
    int tid = threadIdx.x, lane = tid & 31, wid = tid >> 5;
    int wm = wid & 3, wn = wid >> 2;

    const unsigned short* aH = ((MODE == 1) ? g_xgH : g_hbH) + (size_t)m0 * Kd;
    const unsigned short* aL = ((MODE == 1) ? g_xgL : g_hbL) + (size_t)m0 * Kd;
    const unsigned short* bHp;
    const unsigned short* bLp;
    size_t brs;
    if (MODE == 1) { bHp = g_w1H + (size_t)e * Fdim + n0; bLp = g_w1L + (size_t)e * Fdim + n0; brs = EFdim; }
    else           { bHp = g_w2H + (size_t)e * Fdim * Hdim + n0; bLp = g_w2L + (size_t)e * Fdim * Hdim + n0; brs = Hdim; }

    // per-thread load/store coords (one 16B chunk per buffer per thread)
    int ar = tid >> 1, ac = tid & 1;          // A: 128 rows x 2 chunks
    int br = tid >> 4, bc = tid & 15;         // B: 16 rows x 16 chunks
    uint32_t asoff = (uint32_t)(ar * ASTRIDE + ac * 16);
    uint32_t bsoff = (uint32_t)(2 * A_BYTES + br * BSTRIDE + bc * 16);

    uint4 rAh, rAl, rBh, rBl;

#define LDGK(kc) do { \
        size_t agO = (size_t)ar * Kd + (size_t)(kc) * 16 + ac * 8; \
        size_t bgO = ((size_t)(kc) * 16 + br) * brs + bc * 8; \
        rAh = *(const uint4*)(aH  + agO); \
        rAl = *(const uint4*)(aL  + agO); \
        rBh = *(const uint4*)(bHp + bgO); \
        rBl = *(const uint4*)(bLp + bgO); \
    } while (0)

#define STSK(kc) do { \
        char* st = smem + ((kc) & 1) * STAGE; \
        *(uint4*)(st + asoff)           = rAh; \
        *(uint4*)(st + asoff + A_BYTES) = rAl; \
        *(uint4*)(st + bsoff)           = rBh; \
        *(uint4*)(st + bsoff + B_BYTES) = rBl; \
    } while (0)

    float acc[2][8][4];
#pragma unroll
    for (int mt = 0; mt < 2; mt++)
#pragma unroll
        for (int nt = 0; nt < 8; nt++)
#pragma unroll
            for (int i = 0; i < 4; i++) acc[mt][nt][i] = 0.f;

    LDGK(0);
    STSK(0);
    __syncthreads();

    for (int kc = 0; kc < NK; kc++) {
        if (kc + 1 < NK) LDGK(kc + 1);

        uint32_t sA  = sb + (kc & 1) * STAGE;
        uint32_t sBb = sA + 2 * A_BYTES;

        uint32_t a0[2][4], a1[2][4];
#pragma unroll
        for (int mt = 0; mt < 2; mt++) {
            uint32_t ad = sA + (wm * 32 + mt * 16 + (lane & 15)) * ASTRIDE + (lane >> 4) * 16;
            ldm_x4(a0[mt], ad);
            ldm_x4(a1[mt], ad + A_BYTES);
        }
#pragma unroll
        for (int ng = 0; ng < 4; ng++) {
            uint32_t bh[4], bl[4];
            uint32_t bd = sBb + (lane & 15) * BSTRIDE + wn * 128 + ng * 32 + (lane >> 4) * 16;
            ldm_x4t(bh, bd);
            ldm_x4t(bl, bd + B_BYTES);
#pragma unroll
            for (int mt = 0; mt < 2; mt++) {
#pragma unroll
                for (int sub = 0; sub < 2; sub++) {
                    int nt = ng * 2 + sub;
                    mma16816(acc[mt][nt], a0[mt], &bh[sub * 2]);
                    mma16816(acc[mt][nt], a0[mt], &bl[sub * 2]);
                    mma16816(acc[mt][nt], a1[mt], &bh[sub * 2]);
                }
            }
        }

        if (kc + 1 < NK) STSK(kc + 1);
        __syncthreads();
    }

    // ---------------- epilogue ----------------
#pragma unroll
    for (int mt = 0; mt < 2; mt++) {
        int r0 = m0 + wm * 32 + mt * 16 + (lane >> 2);
        int r1 = r0 + 8;
        int tok0 = g_rowTok[r0], tok1 = g_rowTok[r1];
        if (MODE == 1) {
#pragma unroll
            for (int nt = 0; nt < 8; nt++) {
                int c = n0 + wn * 64 + nt * 8 + (lane & 3) * 2;
                if (tok0 >= 0) {
                    float v0 = gelu_exact(acc[mt][nt][0]);
                    float v1 = gelu_exact(acc[mt][nt][1]);
                    unsigned short h0, l0, h1, l1;
                    split2(v0, h0, l0); split2(v1, h1, l1);
                    *(unsigned*)(g_hbH + (size_t)r0 * Fdim + c) = (unsigned)h0 | ((unsigned)h1 << 16);
                    *(unsigned*)(g_hbL + (size_t)r0 * Fdim + c) = (unsigned)l0 | ((unsigned)l1 << 16);
                }
                if (tok1 >= 0) {
                    float v0 = gelu_exact(acc[mt][nt][2]);
                    float v1 = gelu_exact(acc[mt][nt][3]);
                    unsigned short h0, l0, h1, l1;
                    split2(v0, h0, l0); split2(v1, h1, l1);
                    *(unsigned*)(g_hbH + (size_t)r1 * Fdim + c) = (unsigned)h0 | ((unsigned)h1 << 16);
                    *(unsigned*)(g_hbL + (size_t)r1 * Fdim + c) = (unsigned)l0 | ((unsigned)l1 << 16);
                }
            }
        } else {
            float m0f = g_rowMult[r0], m1f = g_rowMult[r1];
#pragma unroll
            for (int nt = 0; nt < 8; nt++) {
                int c = n0 + wn * 64 + nt * 8 + (lane & 3) * 2;
                if (tok0 >= 0) {
                    float* op = dout + (size_t)tok0 * Hdim + c;
                    atomicAdd(&op[0], m0f * acc[mt][nt][0]);
                    atomicAdd(&op[1], m0f * acc[mt][nt][1]);
                }
                if (tok1 >= 0) {
                    float* op = dout + (size_t)tok1 * Hdim + c;
                    atomicAdd(&op[0], m1f * acc[mt][nt][2]);
                    atomicAdd(&op[1], m1f * acc[mt][nt][3]);
                }
            }
        }
    }
#undef LDGK
#undef STSK
}

// ---------------- launch ----------------
extern "C" void kernel_launch(void* const* d_in, const int* in_sizes, int n_in,
                              void* d_out, int out_size) {
    const float* x  = (const float*)d_in[0];
    const float* rw = (const float*)d_in[1];
    const float* w1 = (const float*)d_in[2];
    const float* w2 = (const float*)d_in[3];
    float* out = (float*)d_out;

    float* logits_out;
    if (out_size >= Ttok * Hdim + Ttok * Edim) {
        logits_out = out + (size_t)Ttok * Hdim;
    } else {
        void* p = nullptr;
        cudaGetSymbolAddress(&p, g_logits_scratch);
        logits_out = (float*)p;
    }

    int n4 = (Ttok * Hdim) / 4;
    zero_kernel<<<(n4 + 255) / 256, 256>>>((float4*)out, n4);
    router_kernel<<<Ttok, 256>>>(x, rw, logits_out);
    assign_kernel<<<1, 256>>>();
    gather_split_kernel<<<TKaP, 384>>>(x);
    {
        size_t n2w1 = (size_t)Hdim * EFdim / 2;
        size_t n2w2 = (size_t)EFdim * Hdim / 2;
        split_w_kernel<1><<<(unsigned)((n2w1 + 255) / 256), 256>>>(w1, n2w1);
        split_w_kernel<2><<<(unsigned)((n2w2 + 255) / 256), 256>>>(w2, n2w2);
    }
    mma_kernel<1><<<dim3(Fdim / 128, MAXTILES), 256>>>(nullptr);
    mma_kernel<2><<<dim3(Hdim / 128, MAXTILES), 256>>>(out);
}